// round 15
// baseline (speedup 1.0000x reference)
#include <cuda_runtime.h>
#include <cuda_fp16.h>
#include <cstdint>

// RNN: h_t = tanh([h_{t-1} | x_t] @ [W_hh | W_ih]^T + b), out = h_T @ W_out^T + b_out
// Round 15: ONE CTA PER SM. BTILE=32, grid=128, 4 warps; each warp m=16 x n=32
// (4 independent n-groups -> all latency hiding is in-warp ILP, not arbiter).
// W fp16-split 2-pass, state fp16-only, tanh.approx, direct STS.16 writeback.

#define BATCH    4096
#define TSTEPS   512
#define IN_DIM   28
#define HID      64
#define OUT_DIM  10
#define KCOMB    96            // 64 h + 28 x + 4 pad (fp16 -> 48 words)
#define CHUNKS   6             // KCOMB / 16
#define BTILE    32            // batch rows per CTA
#define NGRP     4             // n-groups of 8 rows per warp
#define NTHREADS 128           // 4 warps, each m=16, n=32
#define S        68            // words per n-row; 68 % 32 == 4 -> conflict-free
#define PLANE    (BTILE * S)   // 2176 words per buffer
#define STATE_WORDS (2 * PLANE)         // 4352 (double buffer)
#define WOUT_OFF 4480                   // W_out stage (past state, inside stage area)
#define BIAS_OFF (HID * KCOMB)          // 6144
#define SMEM_WORDS (BIAS_OFF + HID)     // 6208
#define SMEM_BYTES (SMEM_WORDS * 4)     // 24832 B

#define INV2048  4.8828125e-4f

__device__ __forceinline__ float tanh_hw(float v) {
    float r;
    asm("tanh.approx.f32 %0, %1;" : "=f"(r) : "f"(v));   // MUFU.TANH
    return r;
}

__device__ __forceinline__ uint32_t pack2(__half lo, __half hi) {
    __half2 h = __halves2half2(lo, hi);
    return *reinterpret_cast<uint32_t*>(&h);
}

__device__ __forceinline__ uint32_t packf2(float a, float b) {
    __half2 h = __floats2half2_rn(a, b);
    return *reinterpret_cast<uint32_t*>(&h);
}

__device__ __forceinline__ void mma16(float* d, const uint32_t* a, const uint32_t* b) {
    asm volatile(
        "mma.sync.aligned.m16n8k16.row.col.f32.f16.f16.f32 "
        "{%0,%1,%2,%3}, {%4,%5,%6,%7}, {%8,%9}, {%0,%1,%2,%3};"
        : "+f"(d[0]), "+f"(d[1]), "+f"(d[2]), "+f"(d[3])
        : "r"(a[0]), "r"(a[1]), "r"(a[2]), "r"(a[3]), "r"(b[0]), "r"(b[1]));
}

__global__ void __launch_bounds__(NTHREADS, 1)
rnn_r15_kernel(const float* __restrict__ x,
               const float* __restrict__ W_ih,
               const float* __restrict__ W_hh,
               const float* __restrict__ b_ih,
               const float* __restrict__ b_hh,
               const float* __restrict__ W_out,
               const float* __restrict__ b_out,
               float* __restrict__ out)
{
    extern __shared__ float sm[];
    uint32_t* usm = (uint32_t*)sm;
    __half*   hsm = (__half*)sm;

    const int tid  = threadIdx.x;
    const int b0   = blockIdx.x * BTILE;
    const int lane = tid & 31;
    const int mg   = tid >> 5;     // warp id = m-group: W rows [mg*16, mg*16+16)
    const int gid  = lane >> 2;
    const int tig  = lane & 3;
    const int m0   = mg * 16;

    // ---- Stage combined weight Wc[64][96] fp32 at sm[0..6144) + bias ----
    for (int idx = tid; idx < HID * KCOMB; idx += NTHREADS) {
        int j = idx / KCOMB, k = idx % KCOMB;
        float v = 0.0f;
        if (k < HID)               v = W_hh[j * HID + k];
        else if (k < HID + IN_DIM) v = W_ih[j * IN_DIM + (k - HID)];
        sm[idx] = v;
    }
    if (tid < HID) sm[BIAS_OFF + tid] = b_ih[tid] + b_hh[tid];
    __syncthreads();

    // ---- W fragments (A operand, one m16k16 tile per warp per chunk), hi + lo*2048 ----
    uint32_t whi[CHUNKS][4], wlo[CHUNKS][4];
#pragma unroll
    for (int c = 0; c < CHUNKS; c++) {
#pragma unroll
        for (int r = 0; r < 4; r++) {
            int row = m0 + gid + (r & 1) * 8;
            int k0  = c * 16 + 2 * tig + (r >> 1) * 8;
            float va = sm[row * KCOMB + k0];
            float vb = sm[row * KCOMB + k0 + 1];
            __half ha = __float2half_rn(va), hb = __float2half_rn(vb);
            whi[c][r] = pack2(ha, hb);
            wlo[c][r] = pack2(
                __float2half_rn((va - __half2float(ha)) * 2048.0f),
                __float2half_rn((vb - __half2float(hb)) * 2048.0f));
        }
    }
    const float bias0 = sm[BIAS_OFF + m0 + gid];
    const float bias1 = sm[BIAS_OFF + m0 + gid + 8];
    __syncthreads();   // frag reads done; stage area reused as state

    // ---- Zero state double-buffers (h=0, pads 0) ----
    for (int idx = tid; idx < STATE_WORDS; idx += NTHREADS) sm[idx] = 0.0f;

    // ---- x staging: 224 float4-slots/step spread over 128 threads (1-2 each) ----
    // slot i: row i/7, quarter i%7. Thread t owns slots t and t+128 (if <224).
    const int  i0 = tid,      xn0 = i0 / 7, xq0 = i0 % 7;
    const bool has1 = tid < 96;
    const int  i1 = tid + 128, xn1 = i1 / 7, xq1 = i1 % 7;
    const float4* xp0 = (const float4*)(x + (size_t)(b0 + xn0) * TSTEPS * IN_DIM) + xq0;
    const float4* xp1 = (const float4*)(x + (size_t)(b0 + xn1) * TSTEPS * IN_DIM) + xq1;

    auto store_slot = [&](int p, int xn, int xq, const float4& v) {
        int wb = p * PLANE + xn * S + 32 + 2 * xq;
        uint2 w;
        w.x = packf2(v.x, v.y);
        w.y = packf2(v.z, v.w);
        *reinterpret_cast<uint2*>(&usm[wb]) = w;
    };

    float4 xa0, xa1, xb0, xb1;   // slot0/slot1, t+1 and t+2 in flight
    __syncthreads();                             // zero-fill visible
    {
        float4 v0 = xp0[0];
        store_slot(0, xn0, xq0, v0);
        if (has1) { float4 v1 = xp1[0]; store_slot(0, xn1, xq1, v1); }
        xa0 = xp0[7];                            // x(1)
        if (has1) xb0 = xp1[7];
    }
    __syncthreads();

    const int n0base = 2 * tig;                  // row within group: n0, n0+1

    int p = 0;
    for (int t = 0; t < TSTEPS; t++) {
        if (t + 2 < TSTEPS) {
            xa1 = xp0[(t + 2) * 7];
            if (has1) xb1 = xp1[(t + 2) * 7];
        }

        // 4 groups x 5 chains (accA0/1/2 depth 2, accB1/2 depth 3)
        float accA0[NGRP][4], accA1[NGRP][4], accA2[NGRP][4];
        float accB1[NGRP][4], accB2[NGRP][4];
#pragma unroll
        for (int g = 0; g < NGRP; g++) {
            accA0[g][0] = bias0; accA0[g][1] = bias0;
            accA0[g][2] = bias1; accA0[g][3] = bias1;
#pragma unroll
            for (int r = 0; r < 4; r++) {
                accA1[g][r] = 0.0f; accA2[g][r] = 0.0f;
                accB1[g][r] = 0.0f; accB2[g][r] = 0.0f;
            }
        }

        const int base = p * PLANE + gid * S;    // group 0 row = gid
#pragma unroll
        for (int c = 0; c < CHUNKS; c++) {
#pragma unroll
            for (int g = 0; g < NGRP; g++) {
                const int hbase = base + g * 8 * S;     // 8g*S == 0 mod 32 banks
                uint32_t b[2];
                b[0] = usm[hbase + c * 8 + tig];
                b[1] = usm[hbase + c * 8 + tig + 4];
                if      (c % 3 == 0) mma16(accA0[g], whi[c], b);
                else if (c % 3 == 1) mma16(accA1[g], whi[c], b);
                else                 mma16(accA2[g], whi[c], b);
                if (c & 1) mma16(accB1[g], wlo[c], b);
                else       mma16(accB2[g], wlo[c], b);
            }
        }

        const int q = p ^ 1;
#pragma unroll
        for (int g = 0; g < NGRP; g++) {
            float tA0 = accA0[g][0] + accA1[g][0], tB0 = accB1[g][0] + accB2[g][0];
            float tA1 = accA0[g][1] + accA1[g][1], tB1 = accB1[g][1] + accB2[g][1];
            float tA2 = accA0[g][2] + accA1[g][2], tB2 = accB1[g][2] + accB2[g][2];
            float tA3 = accA0[g][3] + accA1[g][3], tB3 = accB1[g][3] + accB2[g][3];
            float v0 = tanh_hw(tA0 + fmaf(tB0, INV2048, accA2[g][0]));
            float v1 = tanh_hw(tA1 + fmaf(tB1, INV2048, accA2[g][1]));
            float v2 = tanh_hw(tA2 + fmaf(tB2, INV2048, accA2[g][2]));
            float v3 = tanh_hw(tA3 + fmaf(tB3, INV2048, accA2[g][3]));

            // rows g*8 + n0base, +1 ; halfword index = 2*word base + j
            int hb0 = (q * PLANE + (g * 8 + n0base) * S) * 2;
            int hb1 = hb0 + 2 * S;
            int jA = m0 + gid, jB = jA + 8;
            hsm[hb0 + jA] = __float2half_rn(v0);
            hsm[hb1 + jA] = __float2half_rn(v1);
            hsm[hb0 + jB] = __float2half_rn(v2);
            hsm[hb1 + jB] = __float2half_rn(v3);
        }

        if (t + 1 < TSTEPS) {
            store_slot(q, xn0, xq0, xa0);
            if (has1) store_slot(q, xn1, xq1, xb0);
        }
        xa0 = xa1; xb0 = xb1;
        __syncthreads();
        p = q;
    }

    // ---- Output projection: stage W_out past the state region ----
    for (int idx = tid; idx < OUT_DIM * HID; idx += NTHREADS) sm[WOUT_OFF + idx] = W_out[idx];
    if (tid < OUT_DIM) sm[WOUT_OFF + OUT_DIM * HID + tid] = b_out[tid];
    __syncthreads();

    const int hb = p * PLANE;
    for (int idx = tid; idx < BTILE * OUT_DIM; idx += NTHREADS) {
        int n = idx / OUT_DIM, o = idx % OUT_DIM;
        float s = sm[WOUT_OFF + OUT_DIM * HID + o];
#pragma unroll 8
        for (int jp = 0; jp < HID / 2; jp++) {
            __half2 hh = *reinterpret_cast<const __half2*>(&usm[hb + n * S + jp]);
            float2 fh = __half22float2(hh);
            s += fh.x * sm[WOUT_OFF + o * HID + 2 * jp]
               + fh.y * sm[WOUT_OFF + o * HID + 2 * jp + 1];
        }
        out[(size_t)(b0 + n) * OUT_DIM + o] = s;
    }
}

extern "C" void kernel_launch(void* const* d_in, const int* in_sizes, int n_in,
                              void* d_out, int out_size)
{
    const float* x     = (const float*)d_in[0];
    const float* W_ih  = (const float*)d_in[1];
    const float* W_hh  = (const float*)d_in[2];
    const float* b_ih  = (const float*)d_in[3];
    const float* b_hh  = (const float*)d_in[4];
    const float* W_out = (const float*)d_in[5];
    const float* b_out = (const float*)d_in[6];
    float* out = (float*)d_out;

    cudaFuncSetAttribute(rnn_r15_kernel,
                         cudaFuncAttributeMaxDynamicSharedMemorySize, SMEM_BYTES);

    dim3 grid(BATCH / BTILE);   // 128 CTAs -> one per SM, single wave
    dim3 block(NTHREADS);       // 4 warps, each m=16 x n=32
    rnn_r15_kernel<<<grid, block, SMEM_BYTES>>>(x, W_ih, W_hh, b_ih, b_hh,
                                                W_out, b_out, out);
}

// round 16
// speedup vs baseline: 1.0306x; 1.0306x over previous
#include <cuda_runtime.h>
#include <cuda_fp16.h>
#include <cstdint>

// RNN: h_t = tanh([h_{t-1} | x_t] @ [W_hh | W_ih]^T + b), out = h_T @ W_out^T + b_out
// Round 16: WARP-PRIVATE recurrence -- NO block barrier in the 512-step loop.
// Each warp owns 8 batch rows and computes ALL 64 h-columns (m=64 via 4 mtiles).
// W in plain fp16 (one mma pass, 24 mma/warp-step); state fp16 in a warp-private
// smem region (single buffer; within-warp program order + __syncwarp per step).
// 128 CTAs x 4 warps: 1 CTA/SM, wid->SMSP, perfectly balanced single wave.

#define BATCH    4096
#define TSTEPS   512
#define IN_DIM   28
#define HID      64
#define OUT_DIM  10
#define KCOMB    96            // 64 h + 28 x + 4 pad (fp16 -> 48 words)
#define CHUNKS   6             // KCOMB / 16
#define BTILE    32            // batch rows per CTA (8 per warp)
#define NTHREADS 128           // 4 warps
#define NMT      4             // mtiles per warp: m = 64
#define S        52            // words per row (48 data + 4 pad); 52%32=20 -> conflict-free
#define REGION   (8 * S)       // 416 words: one warp's private state (8 rows)
#define STATE_WORDS (4 * REGION)        // 1664 words
#define WOUT_OFF 1664                   // W_out stage (past state)
#define BIAS_OFF (HID * KCOMB)          // 6144 (fp32 W stage, overlaid by state later)
#define SMEM_WORDS (BIAS_OFF + HID)     // 6208
#define SMEM_BYTES (SMEM_WORDS * 4)     // 24832 B

__device__ __forceinline__ float tanh_hw(float v) {
    float r;
    asm("tanh.approx.f32 %0, %1;" : "=f"(r) : "f"(v));   // MUFU.TANH
    return r;
}

__device__ __forceinline__ uint32_t pack2(__half lo, __half hi) {
    __half2 h = __halves2half2(lo, hi);
    return *reinterpret_cast<uint32_t*>(&h);
}

__device__ __forceinline__ uint32_t packf2(float a, float b) {
    __half2 h = __floats2half2_rn(a, b);
    return *reinterpret_cast<uint32_t*>(&h);
}

__device__ __forceinline__ void mma16(float* d, const uint32_t* a, const uint32_t* b) {
    asm volatile(
        "mma.sync.aligned.m16n8k16.row.col.f32.f16.f16.f32 "
        "{%0,%1,%2,%3}, {%4,%5,%6,%7}, {%8,%9}, {%0,%1,%2,%3};"
        : "+f"(d[0]), "+f"(d[1]), "+f"(d[2]), "+f"(d[3])
        : "r"(a[0]), "r"(a[1]), "r"(a[2]), "r"(a[3]), "r"(b[0]), "r"(b[1]));
}

__global__ void __launch_bounds__(NTHREADS, 1)
rnn_r16_kernel(const float* __restrict__ x,
               const float* __restrict__ W_ih,
               const float* __restrict__ W_hh,
               const float* __restrict__ b_ih,
               const float* __restrict__ b_hh,
               const float* __restrict__ W_out,
               const float* __restrict__ b_out,
               float* __restrict__ out)
{
    extern __shared__ float sm[];
    uint32_t* usm = (uint32_t*)sm;
    __half*   hsm = (__half*)sm;

    const int tid  = threadIdx.x;
    const int b0   = blockIdx.x * BTILE;
    const int lane = tid & 31;
    const int wid  = tid >> 5;       // one warp per SMSP
    const int gid  = lane >> 2;
    const int tig  = lane & 3;
    const int wbase = wid * REGION;  // this warp's private state region (words)
    const int rb    = wid * 8;       // this warp's first batch row (CTA-local)

    // ---- Stage combined weight Wc[64][96] fp32 at sm[0..6144) + bias ----
    for (int idx = tid; idx < HID * KCOMB; idx += NTHREADS) {
        int j = idx / KCOMB, k = idx % KCOMB;
        float v = 0.0f;
        if (k < HID)               v = W_hh[j * HID + k];
        else if (k < HID + IN_DIM) v = W_ih[j * IN_DIM + (k - HID)];
        sm[idx] = v;
    }
    if (tid < HID) sm[BIAS_OFF + tid] = b_ih[tid] + b_hh[tid];
    __syncthreads();

    // ---- W fragments: 4 mtiles (m=64) x 6 chunks, plain fp16 ----
    uint32_t whi[NMT][CHUNKS][4];
    float biasA[NMT], biasB[NMT];
#pragma unroll
    for (int mt = 0; mt < NMT; mt++) {
        int m0 = mt * 16;
#pragma unroll
        for (int c = 0; c < CHUNKS; c++) {
#pragma unroll
            for (int r = 0; r < 4; r++) {
                int row = m0 + gid + (r & 1) * 8;
                int k0  = c * 16 + 2 * tig + (r >> 1) * 8;
                whi[mt][c][r] = packf2(sm[row * KCOMB + k0], sm[row * KCOMB + k0 + 1]);
            }
        }
        biasA[mt] = sm[BIAS_OFF + m0 + gid];
        biasB[mt] = sm[BIAS_OFF + m0 + gid + 8];
    }
    __syncthreads();   // frag reads done; stage area reused as state

    // ---- Zero all state regions (h=0, x=0, pads 0) ----
    for (int idx = tid; idx < STATE_WORDS; idx += NTHREADS) sm[idx] = 0.0f;

    // ---- x staging: 56 float4-slots per warp (8 rows x 7 quarters), warp-local ----
    // lane l owns slot l; lanes 0..23 also own slot 32+l.
    const int  xn0 = lane / 7 + ((lane % 7) > lane / 7 ? 0 : 0), dummy0 = 0; (void)dummy0;
    const int  s0 = lane,      a_xn = s0 / 7, a_xq = s0 % 7;
    const bool has1 = lane < 24;
    const int  s1 = lane + 32, b_xn = s1 / 7, b_xq = s1 % 7;
    const float4* xpA = (const float4*)(x + (size_t)(b0 + rb + a_xn) * TSTEPS * IN_DIM) + a_xq;
    const float4* xpB = (const float4*)(x + (size_t)(b0 + rb + b_xn) * TSTEPS * IN_DIM) + b_xq;

    auto store_slot = [&](int xn, int xq, const float4& v) {
        int wb = wbase + xn * S + 32 + 2 * xq;
        uint2 w;
        w.x = packf2(v.x, v.y);
        w.y = packf2(v.z, v.w);
        *reinterpret_cast<uint2*>(&usm[wb]) = w;
    };

    float4 xa0, xa1;                       // slot0: x(t+1), x(t+2)
    float4 xb0 = make_float4(0,0,0,0), xb1 = make_float4(0,0,0,0);
    __syncthreads();                       // zero-fill visible block-wide (once)
    {
        float4 v = xpA[0];  store_slot(a_xn, a_xq, v);          // x(0)
        if (has1) { float4 u = xpB[0]; store_slot(b_xn, b_xq, u); }
        xa0 = xpA[7];                                           // x(1)
        if (has1) xb0 = xpB[7];
    }
    __syncthreads();                       // last block-wide barrier before loop

    const int n0 = 2 * tig;                // output rows n0, n0+1 (0..7)

    for (int t = 0; t < TSTEPS; t++) {
        if (t + 2 < TSTEPS) {
            xa1 = xpA[(t + 2) * 7];
            if (has1) xb1 = xpB[(t + 2) * 7];
        }

        // 4 independent mtile chains, depth 6 each
        float acc[NMT][4];
#pragma unroll
        for (int mt = 0; mt < NMT; mt++) {
            acc[mt][0] = biasA[mt]; acc[mt][1] = biasA[mt];
            acc[mt][2] = biasB[mt]; acc[mt][3] = biasB[mt];
        }

        const int hb = wbase + gid * S;    // B row = gid (0..7), own region
#pragma unroll
        for (int c = 0; c < CHUNKS; c++) {
            uint32_t b2[2];
            b2[0] = usm[hb + c * 8 + tig];
            b2[1] = usm[hb + c * 8 + tig + 4];
#pragma unroll
            for (int mt = 0; mt < NMT; mt++)
                mma16(acc[mt], whi[mt][c], b2);
        }

        // tanh -> fp16 -> direct STS.16 into own region (single buffer)
#pragma unroll
        for (int mt = 0; mt < NMT; mt++) {
            float v0 = tanh_hw(acc[mt][0]);
            float v1 = tanh_hw(acc[mt][1]);
            float v2 = tanh_hw(acc[mt][2]);
            float v3 = tanh_hw(acc[mt][3]);
            int hb0 = (wbase + n0 * S) * 2;      // halfword base, row n0
            int hb1 = hb0 + 2 * S;               // row n0+1
            int jA = mt * 16 + gid, jB = jA + 8;
            hsm[hb0 + jA] = __float2half_rn(v0);
            hsm[hb1 + jA] = __float2half_rn(v1);
            hsm[hb0 + jB] = __float2half_rn(v2);
            hsm[hb1 + jB] = __float2half_rn(v3);
        }

        if (t + 1 < TSTEPS) {
            store_slot(a_xn, a_xq, xa0);
            if (has1) store_slot(b_xn, b_xq, xb0);
        }
        xa0 = xa1; xb0 = xb1;
        __syncwarp();                       // only sync in the loop (~23 cyc)
    }

    // ---- Output projection ----
    __syncthreads();
    for (int idx = tid; idx < OUT_DIM * HID; idx += NTHREADS) sm[WOUT_OFF + idx] = W_out[idx];
    if (tid < OUT_DIM) sm[WOUT_OFF + OUT_DIM * HID + tid] = b_out[tid];
    __syncthreads();

    for (int idx = tid; idx < BTILE * OUT_DIM; idx += NTHREADS) {
        int n = idx / OUT_DIM, o = idx % OUT_DIM;
        int base = (n >> 3) * REGION + (n & 7) * S;   // warp region + row
        float s = sm[WOUT_OFF + OUT_DIM * HID + o];
#pragma unroll 8
        for (int jp = 0; jp < HID / 2; jp++) {
            __half2 hh = *reinterpret_cast<const __half2*>(&usm[base + jp]);
            float2 fh = __half22float2(hh);
            s += fh.x * sm[WOUT_OFF + o * HID + 2 * jp]
               + fh.y * sm[WOUT_OFF + o * HID + 2 * jp + 1];
        }
        out[(size_t)(b0 + n) * OUT_DIM + o] = s;
    }
}

extern "C" void kernel_launch(void* const* d_in, const int* in_sizes, int n_in,
                              void* d_out, int out_size)
{
    const float* x     = (const float*)d_in[0];
    const float* W_ih  = (const float*)d_in[1];
    const float* W_hh  = (const float*)d_in[2];
    const float* b_ih  = (const float*)d_in[3];
    const float* b_hh  = (const float*)d_in[4];
    const float* W_out = (const float*)d_in[5];
    const float* b_out = (const float*)d_in[6];
    float* out = (float*)d_out;

    cudaFuncSetAttribute(rnn_r16_kernel,
                         cudaFuncAttributeMaxDynamicSharedMemorySize, SMEM_BYTES);

    dim3 grid(BATCH / BTILE);   // 128 CTAs -> 1/SM; 4 warp-private RNNs per CTA
    dim3 block(NTHREADS);
    rnn_r16_kernel<<<grid, block, SMEM_BYTES>>>(x, W_ih, W_hh, b_ih, b_hh,
                                                W_out, b_out, out);
}

// round 17
// speedup vs baseline: 1.6381x; 1.5894x over previous
#include <cuda_runtime.h>
#include <cuda_fp16.h>
#include <cstdint>

// RNN: h_t = tanh([h_{t-1} | x_t] @ [W_hh | W_ih]^T + b), out = h_T @ W_out^T + b_out
// Round 17: R16 (warp-private, barrier-free) + 4-deep x LDG register ring.
// At step t: LDG x(t+4) -> slot t&3; consume slot (t+1)&3 (loaded 3 steps ago).
// Removes the ~1030-cyc DRAM latency that sat on EVERY step's critical path.

#define BATCH    4096
#define TSTEPS   512
#define IN_DIM   28
#define HID      64
#define OUT_DIM  10
#define KCOMB    96            // 64 h + 28 x + 4 pad (fp16 -> 48 words)
#define CHUNKS   6             // KCOMB / 16
#define BTILE    32            // batch rows per CTA (8 per warp)
#define NTHREADS 128           // 4 warps, one per SMSP
#define NMT      4             // mtiles per warp: m = 64
#define S        52            // words per row (48 data + 4 pad); 52%32=20 -> conflict-free
#define REGION   (8 * S)       // 416 words: one warp's private state (8 rows)
#define STATE_WORDS (4 * REGION)        // 1664 words
#define WOUT_OFF 1664                   // W_out stage (past state)
#define BIAS_OFF (HID * KCOMB)          // 6144 (fp32 W stage, overlaid by state later)
#define SMEM_WORDS (BIAS_OFF + HID)     // 6208
#define SMEM_BYTES (SMEM_WORDS * 4)     // 24832 B

__device__ __forceinline__ float tanh_hw(float v) {
    float r;
    asm("tanh.approx.f32 %0, %1;" : "=f"(r) : "f"(v));   // MUFU.TANH
    return r;
}

__device__ __forceinline__ uint32_t packf2(float a, float b) {
    __half2 h = __floats2half2_rn(a, b);
    return *reinterpret_cast<uint32_t*>(&h);
}

__device__ __forceinline__ void mma16(float* d, const uint32_t* a, const uint32_t* b) {
    asm volatile(
        "mma.sync.aligned.m16n8k16.row.col.f32.f16.f16.f32 "
        "{%0,%1,%2,%3}, {%4,%5,%6,%7}, {%8,%9}, {%0,%1,%2,%3};"
        : "+f"(d[0]), "+f"(d[1]), "+f"(d[2]), "+f"(d[3])
        : "r"(a[0]), "r"(a[1]), "r"(a[2]), "r"(a[3]), "r"(b[0]), "r"(b[1]));
}

__global__ void __launch_bounds__(NTHREADS, 1)
rnn_r17_kernel(const float* __restrict__ x,
               const float* __restrict__ W_ih,
               const float* __restrict__ W_hh,
               const float* __restrict__ b_ih,
               const float* __restrict__ b_hh,
               const float* __restrict__ W_out,
               const float* __restrict__ b_out,
               float* __restrict__ out)
{
    extern __shared__ float sm[];
    uint32_t* usm = (uint32_t*)sm;
    __half*   hsm = (__half*)sm;

    const int tid  = threadIdx.x;
    const int b0   = blockIdx.x * BTILE;
    const int lane = tid & 31;
    const int wid  = tid >> 5;       // one warp per SMSP
    const int gid  = lane >> 2;
    const int tig  = lane & 3;
    const int wbase = wid * REGION;  // this warp's private state region (words)
    const int rb    = wid * 8;       // this warp's first batch row (CTA-local)

    // ---- Stage combined weight Wc[64][96] fp32 at sm[0..6144) + bias ----
    for (int idx = tid; idx < HID * KCOMB; idx += NTHREADS) {
        int j = idx / KCOMB, k = idx % KCOMB;
        float v = 0.0f;
        if (k < HID)               v = W_hh[j * HID + k];
        else if (k < HID + IN_DIM) v = W_ih[j * IN_DIM + (k - HID)];
        sm[idx] = v;
    }
    if (tid < HID) sm[BIAS_OFF + tid] = b_ih[tid] + b_hh[tid];
    __syncthreads();

    // ---- W fragments: 4 mtiles (m=64) x 6 chunks, plain fp16 ----
    uint32_t whi[NMT][CHUNKS][4];
    float biasA[NMT], biasB[NMT];
#pragma unroll
    for (int mt = 0; mt < NMT; mt++) {
        int m0 = mt * 16;
#pragma unroll
        for (int c = 0; c < CHUNKS; c++) {
#pragma unroll
            for (int r = 0; r < 4; r++) {
                int row = m0 + gid + (r & 1) * 8;
                int k0  = c * 16 + 2 * tig + (r >> 1) * 8;
                whi[mt][c][r] = packf2(sm[row * KCOMB + k0], sm[row * KCOMB + k0 + 1]);
            }
        }
        biasA[mt] = sm[BIAS_OFF + m0 + gid];
        biasB[mt] = sm[BIAS_OFF + m0 + gid + 8];
    }
    __syncthreads();   // frag reads done; stage area reused as state

    // ---- Zero all state regions (h=0, x=0, pads 0) ----
    for (int idx = tid; idx < STATE_WORDS; idx += NTHREADS) sm[idx] = 0.0f;

    // ---- x staging: 56 float4-slots per warp; lane l owns slot l (+ slot 32+l if l<24) ----
    const int  sA = lane,      a_xn = sA / 7, a_xq = sA % 7;
    const bool has1 = lane < 24;
    const int  sB = lane + 32, b_xn = sB / 7, b_xq = sB % 7;
    const float4* xpA = (const float4*)(x + (size_t)(b0 + rb + a_xn) * TSTEPS * IN_DIM) + a_xq;
    const float4* xpB = (const float4*)(x + (size_t)(b0 + rb + b_xn) * TSTEPS * IN_DIM) + b_xq;

    auto store_slot = [&](int xn, int xq, const float4& v) {
        int wb = wbase + xn * S + 32 + 2 * xq;
        uint2 w;
        w.x = packf2(v.x, v.y);
        w.y = packf2(v.z, v.w);
        *reinterpret_cast<uint2*>(&usm[wb]) = w;
    };

    // 4-deep LDG register ring: slot (t+1)&3 holds x(t+1) at step t.
    float4 xa[4], xb[4];
#pragma unroll
    for (int i = 0; i < 4; i++) { xa[i] = make_float4(0,0,0,0); xb[i] = make_float4(0,0,0,0); }

    __syncthreads();                       // zero-fill visible block-wide (once)
    {
        float4 v = xpA[0];  store_slot(a_xn, a_xq, v);          // x(0) -> smem
        if (has1) { float4 u = xpB[0]; store_slot(b_xn, b_xq, u); }
        xa[1] = xpA[7];  xa[2] = xpA[14];  xa[3] = xpA[21];     // x(1..3) in flight
        if (has1) { xb[1] = xpB[7]; xb[2] = xpB[14]; xb[3] = xpB[21]; }
    }
    __syncthreads();                       // last block-wide barrier before loop

    const int n0 = 2 * tig;                // output rows n0, n0+1 (0..7)

#pragma unroll 4
    for (int t = 0; t < TSTEPS; t++) {
        // issue LDG for x(t+4) into slot t&3 -- consumed 3 steps from now
        if (t + 4 < TSTEPS) {
            xa[t & 3] = xpA[(t + 4) * 7];
            if (has1) xb[t & 3] = xpB[(t + 4) * 7];
        }

        // 4 independent mtile chains, depth 6 each
        float acc[NMT][4];
#pragma unroll
        for (int mt = 0; mt < NMT; mt++) {
            acc[mt][0] = biasA[mt]; acc[mt][1] = biasA[mt];
            acc[mt][2] = biasB[mt]; acc[mt][3] = biasB[mt];
        }

        const int hb = wbase + gid * S;    // B row = gid (0..7), own region
#pragma unroll
        for (int c = 0; c < CHUNKS; c++) {
            uint32_t b2[2];
            b2[0] = usm[hb + c * 8 + tig];
            b2[1] = usm[hb + c * 8 + tig + 4];
#pragma unroll
            for (int mt = 0; mt < NMT; mt++)
                mma16(acc[mt], whi[mt][c], b2);
        }

        // tanh -> fp16 -> direct STS.16 into own region (single buffer)
#pragma unroll
        for (int mt = 0; mt < NMT; mt++) {
            float v0 = tanh_hw(acc[mt][0]);
            float v1 = tanh_hw(acc[mt][1]);
            float v2 = tanh_hw(acc[mt][2]);
            float v3 = tanh_hw(acc[mt][3]);
            int hb0 = (wbase + n0 * S) * 2;      // halfword base, row n0
            int hb1 = hb0 + 2 * S;               // row n0+1
            int jA = mt * 16 + gid, jB = jA + 8;
            hsm[hb0 + jA] = __float2half_rn(v0);
            hsm[hb1 + jA] = __float2half_rn(v1);
            hsm[hb0 + jB] = __float2half_rn(v2);
            hsm[hb1 + jB] = __float2half_rn(v3);
        }

        // stage x(t+1) from ring slot (t+1)&3 (loaded 3 steps ago -> no stall)
        if (t + 1 < TSTEPS) {
            store_slot(a_xn, a_xq, xa[(t + 1) & 3]);
            if (has1) store_slot(b_xn, b_xq, xb[(t + 1) & 3]);
        }
        __syncwarp();                       // only sync in the loop
    }

    // ---- Output projection ----
    __syncthreads();
    for (int idx = tid; idx < OUT_DIM * HID; idx += NTHREADS) sm[WOUT_OFF + idx] = W_out[idx];
    if (tid < OUT_DIM) sm[WOUT_OFF + OUT_DIM * HID + tid] = b_out[tid];
    __syncthreads();

    for (int idx = tid; idx < BTILE * OUT_DIM; idx += NTHREADS) {
        int n = idx / OUT_DIM, o = idx % OUT_DIM;
        int base = (n >> 3) * REGION + (n & 7) * S;   // warp region + row
        float s = sm[WOUT_OFF + OUT_DIM * HID + o];
#pragma unroll 8
        for (int jp = 0; jp < HID / 2; jp++) {
            __half2 hh = *reinterpret_cast<const __half2*>(&usm[base + jp]);
            float2 fh = __half22float2(hh);
            s += fh.x * sm[WOUT_OFF + o * HID + 2 * jp]
               + fh.y * sm[WOUT_OFF + o * HID + 2 * jp + 1];
        }
        out[(size_t)(b0 + n) * OUT_DIM + o] = s;
    }
}

extern "C" void kernel_launch(void* const* d_in, const int* in_sizes, int n_in,
                              void* d_out, int out_size)
{
    const float* x     = (const float*)d_in[0];
    const float* W_ih  = (const float*)d_in[1];
    const float* W_hh  = (const float*)d_in[2];
    const float* b_ih  = (const float*)d_in[3];
    const float* b_hh  = (const float*)d_in[4];
    const float* W_out = (const float*)d_in[5];
    const float* b_out = (const float*)d_in[6];
    float* out = (float*)d_out;

    cudaFuncSetAttribute(rnn_r17_kernel,
                         cudaFuncAttributeMaxDynamicSharedMemorySize, SMEM_BYTES);

    dim3 grid(BATCH / BTILE);   // 128 CTAs -> 1/SM; 4 warp-private RNNs per CTA
    dim3 block(NTHREADS);
    rnn_r17_kernel<<<grid, block, SMEM_BYTES>>>(x, W_ih, W_hh, b_ih, b_hh,
                                                W_out, b_out, out);
}